// round 16
// baseline (speedup 1.0000x reference)
#include <cuda_runtime.h>
#include <math.h>
#include <stdint.h>

// Problem dims
constexpr int NB = 64;     // batch
constexpr int NT = 256;    // time
constexpr int ND = 1024;   // input dim
constexpr int NH = 1024;   // hidden
constexpr int NG = 4096;   // 4*NH (gates i,f,g,o)

// Step tiling: block = 64 rows x 256 gate-cols, 512 threads, 8x4 per thread,
// BK=16 cp.async double-buffered, split-K=8, grid 128 blocks (one per SM).
constexpr int JT     = 64;       // h-columns per block tile
constexpr int NJT    = NH / JT;  // 16 j-tiles
constexpr int NSPLIT = 8;        // K splits per layer-step
constexpr int BK     = 16;       // k-chunk for W streaming
constexpr int GRID   = NJT * NSPLIT;  // 128 blocks

// ---------------------------------------------------------------------------
// Scratch state (device globals: allocation-free per harness rules)
// ---------------------------------------------------------------------------
__device__ float g_xpre[(size_t)NT * NB * NG];  // x @ Wx0 + b0  (256 MB)
__device__ float g_h0[2][NB * NH];              // ping-pong by t parity
__device__ float g_h1[2][NB * NH];
__device__ float g_c0[NB * NH];
__device__ float g_c1[NB * NH];
__device__ float g_part[NSPLIT][NB * NG];       // split-K partial gates (8 MB)
__device__ int   g_cnt[2][NJT];                 // monotonic per (layer,jtile)
__device__ int   g_gbar;                        // monotonic grid barrier

// ---------------------------------------------------------------------------
// Packed f32x2 helpers (Blackwell packed fp32: 2x FFMA throughput)
// ---------------------------------------------------------------------------
__device__ __forceinline__ unsigned long long dup2(float v) {
    unsigned long long r;
    asm("mov.b64 %0, {%1, %1};" : "=l"(r) : "f"(v));
    return r;
}
__device__ __forceinline__ void fma2(unsigned long long& acc,
                                     unsigned long long a, unsigned long long b) {
    asm("fma.rn.f32x2 %0, %1, %2, %0;" : "+l"(acc) : "l"(a), "l"(b));
}
__device__ __forceinline__ void unpack2(unsigned long long v, float& lo, float& hi) {
    asm("mov.b64 {%0, %1}, %2;" : "=f"(lo), "=f"(hi) : "l"(v));
}
__device__ __forceinline__ unsigned long long pack2(float lo, float hi) {
    unsigned long long r;
    asm("mov.b64 %0, {%1, %2};" : "=l"(r) : "f"(lo), "f"(hi));
    return r;
}
__device__ __forceinline__ float sig_(float x)  { return 1.0f / (1.0f + __expf(-x)); }
__device__ __forceinline__ float tanh_(float x) {
    float e = __expf(2.0f * x);            // inf-safe: e=inf -> 1, e=0 -> -1
    return 1.0f - 2.0f / (e + 1.0f);
}
__device__ __forceinline__ void cp16(uint32_t dst, const void* src) {
    asm volatile("cp.async.cg.shared.global [%0], [%1], 16;" :: "r"(dst), "l"(src));
}

// ---------------------------------------------------------------------------
// Zero recurrent state + counters (graph replays reuse device globals)
// ---------------------------------------------------------------------------
__global__ void init_state_kernel() {
    int i = blockIdx.x * blockDim.x + threadIdx.x;
    if (i < NB * NH) {
        g_h0[0][i] = 0.f; g_h0[1][i] = 0.f;
        g_h1[0][i] = 0.f; g_h1[1][i] = 0.f;
        g_c0[i] = 0.f;    g_c1[i] = 0.f;
    }
    if (i < 2 * NJT) ((int*)g_cnt)[i] = 0;
    if (i == 0) g_gbar = 0;
}

// ---------------------------------------------------------------------------
// Precompute: Xpre[(t*NB+b)][n] = sum_k x[b][t][k] * Wx0[k][n] + b0[n]
// (unchanged from prior passing rounds)
// ---------------------------------------------------------------------------
__global__ __launch_bounds__(256) void precompute_kernel(
    const float* __restrict__ x, const float* __restrict__ Wx0,
    const float* __restrict__ b0)
{
    constexpr int PBK = 16;
    __shared__ float As[PBK][132];
    __shared__ float Ws[PBK][64];

    const int tid = threadIdx.x;
    const int tc = tid & 15;
    const int tr = tid >> 4;
    const int col0 = blockIdx.x * 64;
    const int row0 = blockIdx.y * 128;

    unsigned long long acc[8][2];
#pragma unroll
    for (int i = 0; i < 8; i++) { acc[i][0] = 0ull; acc[i][1] = 0ull; }

    for (int k0 = 0; k0 < ND; k0 += PBK) {
#pragma unroll
        for (int i = 0; i < 2; i++) {
            int idx = tid + i * 256;
            int r   = idx & 127;
            int kq  = (idx >> 7) << 2;
            int grow = row0 + r;
            int tt = grow >> 6;
            int bb = grow & 63;
            float4 v = *(const float4*)&x[((size_t)bb * NT + tt) * ND + k0 + kq];
            As[kq + 0][r] = v.x; As[kq + 1][r] = v.y;
            As[kq + 2][r] = v.z; As[kq + 3][r] = v.w;
        }
        {
            int kk = tid >> 4;
            int nq = (tid & 15) << 2;
            *(float4*)&Ws[kk][nq] =
                *(const float4*)&Wx0[(size_t)(k0 + kk) * NG + col0 + nq];
        }
        __syncthreads();

#pragma unroll
        for (int kk = 0; kk < PBK; kk++) {
            float4 a0 = *(const float4*)&As[kk][tr * 8];
            float4 a1 = *(const float4*)&As[kk][tr * 8 + 4];
            float4 wv = *(const float4*)&Ws[kk][tc * 4];
            unsigned long long w01 = pack2(wv.x, wv.y);
            unsigned long long w23 = pack2(wv.z, wv.w);
            float ar[8] = {a0.x, a0.y, a0.z, a0.w, a1.x, a1.y, a1.z, a1.w};
#pragma unroll
            for (int i = 0; i < 8; i++) {
                unsigned long long ad = dup2(ar[i]);
                fma2(acc[i][0], ad, w01);
                fma2(acc[i][1], ad, w23);
            }
        }
        __syncthreads();
    }

    const int c = col0 + tc * 4;
    float4 bb4 = *(const float4*)&b0[c];
#pragma unroll
    for (int i = 0; i < 8; i++) {
        int grow = row0 + tr * 8 + i;
        float v0, v1, v2, v3;
        unpack2(acc[i][0], v0, v1);
        unpack2(acc[i][1], v2, v3);
        float4 o;
        o.x = v0 + bb4.x; o.y = v1 + bb4.y; o.z = v2 + bb4.z; o.w = v3 + bb4.w;
        *(float4*)&g_xpre[(size_t)grow * NG + c] = o;
    }
}

// ---------------------------------------------------------------------------
// Persistent recurrence kernel: 512 layer-phases in ONE launch.
// Phase p = t*2 + layer.
//   layer 0: gates = Xpre[t] + h0_prev @ Wh0            (K=1024, 8 splits x 128)
//   layer 1: gates = b1 + h0_new @ Wx1 + h1_prev @ Wh1  (K=2048, 8 splits x 256)
// 128 blocks x 512 thr, all co-resident (1 block/SM). Per phase: split-K GEMM
// partials -> per-j-tile rendezvous (monotonic counters) -> cooperative cell
// update -> cross-phase W prefetch -> monotonic grid barrier.
// ---------------------------------------------------------------------------
__global__ __launch_bounds__(512, 1) void lstm_persistent_kernel(
    const float* __restrict__ Wh0, const float* __restrict__ Wx1,
    const float* __restrict__ Wh1, const float* __restrict__ b1)
{
    extern __shared__ float sdyn[];
    float* Asl = sdyn;                       // [Ksp<=256][64]   (64 KB)
    float* Wsl = sdyn + 256 * 64;            // [2][BK][256]     (32 KB)

    const int tid = threadIdx.x;     // 512
    const int tc  = tid & 63;        // 64 col-threads * 4 cols = 256
    const int tr  = tid >> 6;        // 8 row-threads * 8 rows = 64
    const int bid = blockIdx.x;      // 0..127
    const int jt  = bid & 15;        // j-tile
    const int sp  = bid >> 4;        // split
    const int j0  = jt * JT;

    const uint32_t wbase = (uint32_t)__cvta_generic_to_shared(Wsl);

    // phase -> (A, W, k0, Ksp) for this block's split
    auto phase_AW = [&](int p, const float*& A, const float*& W,
                        int& k0, int& Ksp) {
        const int tt = p >> 1, layer = p & 1;
        const int cur = tt & 1, nxt = cur ^ 1;
        if (layer == 0) {
            Ksp = ND / NSPLIT;                        // 128
            A = g_h0[cur]; W = Wh0; k0 = sp * Ksp;
        } else {
            Ksp = 2048 / NSPLIT;                      // 256
            if (sp < 4) { A = g_h0[nxt]; W = Wx1; k0 = sp * Ksp; }
            else        { A = g_h1[cur]; W = Wh1; k0 = (sp - 4) * Ksp; }
        }
    };

    // cp.async W chunk ch of (W,k0) into buffer b: 16 k x 256 cols
    auto issueW = [&](const float* W, int k0, int ch, int b) {
        const int kc = k0 + ch * BK;
#pragma unroll
        for (int i = 0; i < 2; i++) {
            int idx = tid + i * 512;             // 0..1023
            int kk  = idx >> 6;                  // 0..15
            int rem = idx & 63;                  // float4 group within 256 cols
            const float* src =
                &W[(size_t)(kc + kk) * NG + (rem >> 4) * NH + j0 + ((rem & 15) << 2)];
            uint32_t dst = wbase + (uint32_t)(((b * BK + kk) * 256 + (rem << 2)) * 4);
            cp16(dst, src);
        }
        asm volatile("cp.async.commit_group;" ::: "memory");
    };

    // prefetch phase 0 chunk 0
    {
        const float *A, *W; int k0, Ksp;
        phase_AW(0, A, W, k0, Ksp);
        issueW(W, k0, 0, 0);
    }

    for (int p = 0; p < 2 * NT; p++) {
        const int t = p >> 1, layer = p & 1;
        const int cur = t & 1, nxt = cur ^ 1;
        const float *A, *W; int k0, Ksp;
        phase_AW(p, A, W, k0, Ksp);
        float* cS   = layer ? g_c1 : g_c0;
        float* hOut = layer ? g_h1[nxt] : g_h0[nxt];
        const int NCH = Ksp / BK;                // 8 (L0) or 16 (L1)

        // Preload A slice [Ksp][64] transposed into smem (h ready: barrier'd)
        {
            const int tot4 = Ksp * 16;
            for (int f = tid; f < tot4; f += 512) {
                int r  = f & 63;
                int jq = f >> 6;
                float4 v = *(const float4*)&A[(size_t)r * NH + k0 + jq * 4];
                float* dst = &Asl[(jq * 4) * 64 + r];
                dst[0] = v.x; dst[64] = v.y; dst[128] = v.z; dst[192] = v.w;
            }
        }

        unsigned long long acc[4][4];
#pragma unroll
        for (int q = 0; q < 4; q++)
#pragma unroll
            for (int c = 0; c < 4; c++) acc[q][c] = 0ull;

        int buf = 0;
        for (int ch = 0; ch < NCH; ch++) {
            asm volatile("cp.async.wait_group 0;" ::: "memory");
            __syncthreads();                     // Ws[buf] ready; buf^1 free
            if (ch + 1 < NCH) issueW(W, k0, ch + 1, buf ^ 1);

            const float* Ak = Asl + (ch * BK) * 64 + tr * 8;
            const float* Wk = Wsl + (buf * BK) * 256 + tc * 4;

            ulonglong2 a0 = *(const ulonglong2*)(Ak);
            ulonglong2 a1 = *(const ulonglong2*)(Ak + 4);
            float4     w  = *(const float4*)(Wk);
#pragma unroll
            for (int kk = 0; kk < BK; kk++) {
                ulonglong2 b0v, b1v; float4 wn;
                if (kk + 1 < BK) {
                    b0v = *(const ulonglong2*)(Ak + (kk + 1) * 64);
                    b1v = *(const ulonglong2*)(Ak + (kk + 1) * 64 + 4);
                    wn  = *(const float4*)(Wk + (kk + 1) * 256);
                }
                unsigned long long wd[4] = {dup2(w.x), dup2(w.y), dup2(w.z), dup2(w.w)};
                unsigned long long ap[4] = {a0.x, a0.y, a1.x, a1.y};
#pragma unroll
                for (int q = 0; q < 4; q++)
#pragma unroll
                    for (int c = 0; c < 4; c++) fma2(acc[q][c], ap[q], wd[c]);
                a0 = b0v; a1 = b1v; w = wn;
            }
            buf ^= 1;
        }

        // write split partial: 8 rows x 4 cols per thread
        {
            float* P = g_part[sp];
            const int bc   = tc * 4;
            const int gcol = (bc >> 6) * NH + j0 + (bc & 63);
#pragma unroll
            for (int q = 0; q < 4; q++) {
                int r0 = tr * 8 + q * 2;
                float lo[4], hi[4];
#pragma unroll
                for (int j = 0; j < 4; j++) unpack2(acc[q][j], lo[j], hi[j]);
                *(float4*)&P[(size_t)r0 * NG + gcol] =
                    make_float4(lo[0], lo[1], lo[2], lo[3]);
                *(float4*)&P[(size_t)(r0 + 1) * NG + gcol] =
                    make_float4(hi[0], hi[1], hi[2], hi[3]);
            }
        }

        // rendezvous: the 8 split blocks of this j-tile (monotonic counter)
        __threadfence();
        __syncthreads();
        if (tid == 0) {
            atomicAdd(&g_cnt[layer][jt], 1);
            const int target = (t + 1) * NSPLIT;
            volatile int* cp = &g_cnt[layer][jt];
            while (*cp < target) { __nanosleep(32); }
            __threadfence();
        }
        __syncthreads();

        // cooperative reduction + cell update: block's split takes 8 rows
        {
            const int r   = sp * 8 + (tid >> 6);
            const int col = j0 + (tid & 63);
            float gi = 0.f, gf = 0.f, gg = 0.f, go = 0.f;
#pragma unroll
            for (int s = 0; s < NSPLIT; s++) {
                const float* P = g_part[s] + (size_t)r * NG + col;
                gi += P[0]; gf += P[NH]; gg += P[2 * NH]; go += P[3 * NH];
            }
            if (layer == 0) {
                const float* xp = g_xpre + (size_t)t * NB * NG + (size_t)r * NG + col;
                gi += xp[0]; gf += xp[NH]; gg += xp[2 * NH]; go += xp[3 * NH];
            } else {
                const float* bp = b1 + col;
                gi += bp[0]; gf += bp[NH]; gg += bp[2 * NH]; go += bp[3 * NH];
            }
            int ci = r * NH + col;
            float cv = cS[ci];
            float is = sig_(gi), fs = sig_(gf);
            float gt = tanh_(gg), os = sig_(go);
            float cn = fs * cv + is * gt;
            cS[ci]   = cn;
            hOut[ci] = os * tanh_(cn);
        }

        // prefetch next phase's W chunk 0 into buffer 0 (free: last compute
        // used buffer (NCH-1)&1 = 1) BEFORE the barrier, hiding cold start
        if (p + 1 < 2 * NT) {
            const float *An, *Wn; int k0n, Kspn;
            phase_AW(p + 1, An, Wn, k0n, Kspn);
            issueW(Wn, k0n, 0, 0);
        }

        // grid barrier (monotonic): all h/c writes visible before next phase
        __threadfence();
        __syncthreads();
        if (tid == 0) {
            atomicAdd(&g_gbar, 1);
            const int target = (p + 1) * GRID;
            volatile int* gp = &g_gbar;
            while (*gp < target) { __nanosleep(32); }
            __threadfence();
        }
        __syncthreads();
    }
}

// ---------------------------------------------------------------------------
// Copy final top-layer hidden state to output. After t = NT-1 (odd), layer1
// wrote g_h1[nxt = 0].
// ---------------------------------------------------------------------------
__global__ void copy_out_kernel(float* __restrict__ out) {
    int i = blockIdx.x * blockDim.x + threadIdx.x;
    if (i < NB * NH) out[i] = g_h1[0][i];
}

// ---------------------------------------------------------------------------
// kernel_launch: graph-capturable, allocation-free, deterministic.
// Inputs: x, Wx0, Wh0, b0, Wx1, Wh1, b1. Output: h1 [64,1024] fp32.
// ---------------------------------------------------------------------------
extern "C" void kernel_launch(void* const* d_in, const int* in_sizes, int n_in,
                              void* d_out, int out_size) {
    const float* x   = (const float*)d_in[0];
    const float* Wx0 = (const float*)d_in[1];
    const float* Wh0 = (const float*)d_in[2];
    const float* b0  = (const float*)d_in[3];
    const float* Wx1 = (const float*)d_in[4];
    const float* Wh1 = (const float*)d_in[5];
    const float* b1  = (const float*)d_in[6];
    float* out = (float*)d_out;

    (void)in_sizes; (void)n_in; (void)out_size;

    constexpr int SMEM_STEP = (256 * 64 + 2 * BK * 256) * 4;  // 96 KB
    cudaFuncSetAttribute(lstm_persistent_kernel,
                         cudaFuncAttributeMaxDynamicSharedMemorySize, SMEM_STEP);

    init_state_kernel<<<(NB * NH + 255) / 256, 256>>>();

    // Phase 1: all-timestep input projection for layer 0
    precompute_kernel<<<dim3(NG / 64, (NT * NB) / 128), 256>>>(x, Wx0, b0);

    // Phase 2: whole recurrence in ONE persistent launch (128 co-resident blocks)
    lstm_persistent_kernel<<<GRID, 512, SMEM_STEP>>>(Wh0, Wx1, Wh1, b1);

    copy_out_kernel<<<(NB * NH + 1023) / 1024, 1024>>>(out);
}